// round 2
// baseline (speedup 1.0000x reference)
#include <cuda_runtime.h>
#include <math_constants.h>

// Problem constants
#define B_   16
#define D_   256
#define T_   4096
#define NQ_  8
#define BINS_ 1024
#define N_   (B_ * T_)          // 65536 vectors

#define QUANT_ELEMS (B_ * D_ * T_)   // 16,777,216
#define CODES_ELEMS (NQ_ * N_)       // 524,288

// Scratch (device globals; allocation is forbidden)
__device__ float g_resid[(size_t)N_ * D_];     // 64 MB
__device__ int   g_codes[NQ_ * N_];            // 2 MB
__device__ float g_cnorm[NQ_ * BINS_];         // 32 KB
__device__ float g_loss;

// ---------------------------------------------------------------------------
// zero the loss accumulator
__global__ void zero_loss_kernel() { g_loss = 0.0f; }

// ---------------------------------------------------------------------------
// codebook squared norms: one warp per (q, bin) row
__global__ void cnorm_kernel(const float* __restrict__ cb) {
    int row  = blockIdx.x * 8 + (threadIdx.x >> 5);   // 0 .. NQ*BINS-1
    int lane = threadIdx.x & 31;
    const float4* c4 = (const float4*)(cb + (size_t)row * D_);
    float s = 0.0f;
    #pragma unroll
    for (int i = lane; i < D_ / 4; i += 32) {
        float4 v = c4[i];
        s += v.x * v.x + v.y * v.y + v.z * v.z + v.w * v.w;
    }
    #pragma unroll
    for (int o = 16; o > 0; o >>= 1) s += __shfl_xor_sync(0xFFFFFFFFu, s, o);
    if (lane == 0) g_cnorm[row] = s;
}

// ---------------------------------------------------------------------------
// transpose x [B][D][T] -> residual [B*T][D]
__global__ void transpose_in_kernel(const float* __restrict__ x) {
    __shared__ float tile[32][33];
    int b  = blockIdx.z;
    int d0 = blockIdx.y * 32;
    int t0 = blockIdx.x * 32;
    int tx = threadIdx.x;  // 0..31
    int ty = threadIdx.y;  // 0..7
    #pragma unroll
    for (int i = ty; i < 32; i += 8)
        tile[i][tx] = x[(size_t)b * D_ * T_ + (size_t)(d0 + i) * T_ + t0 + tx];
    __syncthreads();
    #pragma unroll
    for (int i = ty; i < 32; i += 8)
        g_resid[((size_t)b * T_ + t0 + i) * D_ + d0 + tx] = tile[tx][i];
}

// ---------------------------------------------------------------------------
// fused distance + argmin: block = 64 rows x all 1024 bins
// dist(n,j) = ||c_j||^2 - 2 * r_n . c_j   (row-constant ||r||^2 dropped)
__global__ __launch_bounds__(256) void dist_argmin_kernel(
    const float* __restrict__ cb_all,  // [NQ][BINS][D]
    int q_layer)
{
    __shared__ float As[64][17];
    __shared__ float Bs[64][17];
    __shared__ float sv[64][17];
    __shared__ int   si[64][17];

    const float* cb    = cb_all + (size_t)q_layer * BINS_ * D_;
    const float* cnorm = g_cnorm + q_layer * BINS_;
    int*         codes = g_codes + q_layer * N_;

    const int n0  = blockIdx.x * 64;
    const int tid = threadIdx.x;
    const int ty  = tid >> 4;   // 0..15 : row group (4 rows each)
    const int tx  = tid & 15;   // 0..15 : col group (4 cols each)

    float bestv[4];
    int   besti[4];
    #pragma unroll
    for (int m = 0; m < 4; m++) { bestv[m] = CUDART_INF_F; besti[m] = 0; }

    const int lr = tid >> 2;          // 0..63 (row for tile loads)
    const int lk = (tid & 3) * 4;     // 0,4,8,12 (k offset, float4)

    for (int j0 = 0; j0 < BINS_; j0 += 64) {
        float acc[4][4];
        #pragma unroll
        for (int m = 0; m < 4; m++)
            #pragma unroll
            for (int n = 0; n < 4; n++) acc[m][n] = 0.0f;

        for (int k0 = 0; k0 < D_; k0 += 16) {
            float4 av = *(const float4*)&g_resid[((size_t)(n0 + lr)) * D_ + k0 + lk];
            float4 bv = *(const float4*)&cb[(size_t)(j0 + lr) * D_ + k0 + lk];
            As[lr][lk + 0] = av.x; As[lr][lk + 1] = av.y;
            As[lr][lk + 2] = av.z; As[lr][lk + 3] = av.w;
            Bs[lr][lk + 0] = bv.x; Bs[lr][lk + 1] = bv.y;
            Bs[lr][lk + 2] = bv.z; Bs[lr][lk + 3] = bv.w;
            __syncthreads();
            #pragma unroll
            for (int k = 0; k < 16; k++) {
                float a0 = As[ty * 4 + 0][k];
                float a1 = As[ty * 4 + 1][k];
                float a2 = As[ty * 4 + 2][k];
                float a3 = As[ty * 4 + 3][k];
                float b0 = Bs[tx * 4 + 0][k];
                float b1 = Bs[tx * 4 + 1][k];
                float b2 = Bs[tx * 4 + 2][k];
                float b3 = Bs[tx * 4 + 3][k];
                acc[0][0] += a0 * b0; acc[0][1] += a0 * b1; acc[0][2] += a0 * b2; acc[0][3] += a0 * b3;
                acc[1][0] += a1 * b0; acc[1][1] += a1 * b1; acc[1][2] += a1 * b2; acc[1][3] += a1 * b3;
                acc[2][0] += a2 * b0; acc[2][1] += a2 * b1; acc[2][2] += a2 * b2; acc[2][3] += a2 * b3;
                acc[3][0] += a3 * b0; acc[3][1] += a3 * b1; acc[3][2] += a3 * b2; acc[3][3] += a3 * b3;
            }
            __syncthreads();
        }

        #pragma unroll
        for (int m = 0; m < 4; m++) {
            #pragma unroll
            for (int n = 0; n < 4; n++) {
                int   j = j0 + tx * 4 + n;
                float d = cnorm[j] - 2.0f * acc[m][n];
                if (d < bestv[m] || (d == bestv[m] && j < besti[m])) {
                    bestv[m] = d;
                    besti[m] = j;
                }
            }
        }
    }

    // cross-thread reduce: row r is held by the 16 threads with ty == r/4
    #pragma unroll
    for (int m = 0; m < 4; m++) {
        sv[ty * 4 + m][tx] = bestv[m];
        si[ty * 4 + m][tx] = besti[m];
    }
    __syncthreads();
    if (tid < 64) {
        float bv = sv[tid][0];
        int   bi = si[tid][0];
        #pragma unroll
        for (int xk = 1; xk < 16; xk++) {
            float v = sv[tid][xk];
            int   i = si[tid][xk];
            if (v < bv || (v == bv && i < bi)) { bv = v; bi = i; }
        }
        codes[n0 + tid] = bi;
    }
}

// ---------------------------------------------------------------------------
// update: q = cb[idx]; loss += sum((r - q)^2); r -= q
__global__ __launch_bounds__(256) void update_kernel(
    const float* __restrict__ cb_all, int q_layer)
{
    __shared__ float warp_ss[8];
    const float* cb    = cb_all + (size_t)q_layer * BINS_ * D_;
    const int*   codes = g_codes + q_layer * N_;

    int warp = threadIdx.x >> 5;
    int lane = threadIdx.x & 31;
    int n    = blockIdx.x * 8 + warp;

    const float4* q4 = (const float4*)(cb + (size_t)codes[n] * D_);
    float4* r4 = (float4*)(g_resid + (size_t)n * D_);

    float ss = 0.0f;
    #pragma unroll
    for (int i = 0; i < 2; i++) {
        int e = lane + 32 * i;          // 64 float4 per row
        float4 r = r4[e];
        float4 q = q4[e];
        float dx = r.x - q.x, dy = r.y - q.y, dz = r.z - q.z, dw = r.w - q.w;
        ss += dx * dx + dy * dy + dz * dz + dw * dw;
        r4[e] = make_float4(dx, dy, dz, dw);
    }
    #pragma unroll
    for (int o = 16; o > 0; o >>= 1) ss += __shfl_xor_sync(0xFFFFFFFFu, ss, o);
    if (lane == 0) warp_ss[warp] = ss;
    __syncthreads();
    if (threadIdx.x == 0) {
        float s = 0.0f;
        #pragma unroll
        for (int w = 0; w < 8; w++) s += warp_ss[w];
        atomicAdd(&g_loss, s);
    }
}

// ---------------------------------------------------------------------------
// quantized = x - residual_final, transposed back to [B][D][T]
__global__ void finalize_out_kernel(const float* __restrict__ x,
                                    float* __restrict__ out)
{
    __shared__ float tile[32][33];
    int b  = blockIdx.z;
    int d0 = blockIdx.y * 32;
    int t0 = blockIdx.x * 32;
    int tx = threadIdx.x;
    int ty = threadIdx.y;
    #pragma unroll
    for (int i = ty; i < 32; i += 8)   // load resid tile: coalesced in d
        tile[i][tx] = g_resid[((size_t)b * T_ + t0 + i) * D_ + d0 + tx];
    __syncthreads();
    #pragma unroll
    for (int i = ty; i < 32; i += 8) { // write coalesced in t
        size_t xi = (size_t)b * D_ * T_ + (size_t)(d0 + i) * T_ + t0 + tx;
        out[xi] = x[xi] - tile[tx][i];
    }
}

// ---------------------------------------------------------------------------
__global__ void codes_to_float_kernel(float* __restrict__ out) {
    int i = blockIdx.x * 256 + threadIdx.x;
    if (i < CODES_ELEMS) out[i] = (float)g_codes[i];
}

__global__ void loss_write_kernel(float* __restrict__ out) {
    out[0] = g_loss * (1.0f / ((float)NQ_ * (float)N_ * (float)D_));
}

// ---------------------------------------------------------------------------
extern "C" void kernel_launch(void* const* d_in, const int* in_sizes, int n_in,
                              void* d_out, int out_size)
{
    const float* x  = (const float*)d_in[0];   // [B, D, T]
    const float* cb = (const float*)d_in[1];   // [NQ, BINS, D]
    float* out = (float*)d_out;

    zero_loss_kernel<<<1, 1>>>();
    cnorm_kernel<<<(NQ_ * BINS_) / 8, 256>>>(cb);
    {
        dim3 grid(T_ / 32, D_ / 32, B_);
        dim3 blk(32, 8);
        transpose_in_kernel<<<grid, blk>>>(x);
    }
    for (int q = 0; q < NQ_; q++) {
        dist_argmin_kernel<<<N_ / 64, 256>>>(cb, q);
        update_kernel<<<N_ / 8, 256>>>(cb, q);
    }
    {
        dim3 grid(T_ / 32, D_ / 32, B_);
        dim3 blk(32, 8);
        finalize_out_kernel<<<grid, blk>>>(x, out);
    }
    codes_to_float_kernel<<<(CODES_ELEMS + 255) / 256, 256>>>(out + QUANT_ELEMS);
    loss_write_kernel<<<1, 1>>>(out + QUANT_ELEMS + CODES_ELEMS);
}

// round 3
// speedup vs baseline: 1.4588x; 1.4588x over previous
#include <cuda_runtime.h>
#include <math_constants.h>

// Problem constants
#define B_    16
#define D_    256
#define T_    4096
#define NQ_   8
#define BINS_ 1024
#define N_    (B_ * T_)              // 65536 vectors

#define QUANT_ELEMS (B_ * D_ * T_)   // 16,777,216
#define CODES_ELEMS (NQ_ * N_)       // 524,288

// Scratch (device globals; allocation is forbidden)
__device__ float g_resid[(size_t)N_ * D_];     // 64 MB
__device__ int   g_codes[NQ_ * N_];            // 2 MB
__device__ float g_cnorm[NQ_ * BINS_];         // 32 KB
__device__ float g_loss;

// ---------------------------------------------------------------------------
__global__ void zero_loss_kernel() { g_loss = 0.0f; }

// ---------------------------------------------------------------------------
// codebook squared norms: one warp per (q, bin) row
__global__ void cnorm_kernel(const float* __restrict__ cb) {
    int row  = blockIdx.x * 8 + (threadIdx.x >> 5);   // 0 .. NQ*BINS-1
    int lane = threadIdx.x & 31;
    const float4* c4 = (const float4*)(cb + (size_t)row * D_);
    float s = 0.0f;
    #pragma unroll
    for (int i = lane; i < D_ / 4; i += 32) {
        float4 v = c4[i];
        s += v.x * v.x + v.y * v.y + v.z * v.z + v.w * v.w;
    }
    #pragma unroll
    for (int o = 16; o > 0; o >>= 1) s += __shfl_xor_sync(0xFFFFFFFFu, s, o);
    if (lane == 0) g_cnorm[row] = s;
}

// ---------------------------------------------------------------------------
// transpose x [B][D][T] -> residual [B*T][D]
__global__ void transpose_in_kernel(const float* __restrict__ x) {
    __shared__ float tile[32][33];
    int b  = blockIdx.z;
    int d0 = blockIdx.y * 32;
    int t0 = blockIdx.x * 32;
    int tx = threadIdx.x;
    int ty = threadIdx.y;
    #pragma unroll
    for (int i = ty; i < 32; i += 8)
        tile[i][tx] = x[(size_t)b * D_ * T_ + (size_t)(d0 + i) * T_ + t0 + tx];
    __syncthreads();
    #pragma unroll
    for (int i = ty; i < 32; i += 8)
        g_resid[((size_t)b * T_ + t0 + i) * D_ + d0 + tx] = tile[tx][i];
}

// ---------------------------------------------------------------------------
// fused distance + argmin: block = 128 rows x all 1024 bins (128-bin chunks)
// dist(n,j) = ||c_j||^2 - 2 * r_n . c_j   (row-constant ||r||^2 dropped)
// 8x8 register microtile, k-major smem tiles -> 4 LDS.128 per 64 FFMA.
__global__ __launch_bounds__(256, 2) void dist_argmin_kernel(
    const float* __restrict__ cb_all,  // [NQ][BINS][D]
    int q_layer)
{
    __shared__ union {
        struct { float A[16][132]; float B[16][132]; } g;
        struct { float v[128][17]; int idx[128][17]; } r;
    } sm;

    const float* cb    = cb_all + (size_t)q_layer * BINS_ * D_;
    const float* cnorm = g_cnorm + q_layer * BINS_;
    int*         codes = g_codes + q_layer * N_;

    const int tid = threadIdx.x;
    const int tx  = tid & 15;          // 0..15 : col group (8 cols)
    const int ty  = tid >> 4;          // 0..15 : row group (8 rows)
    const int n0  = blockIdx.x * 128;

    const int lr = tid >> 2;           // 0..63 : row for tile loads
    const int lk = (tid & 3) << 2;     // 0,4,8,12 : k offset (float4)

    float bestv[8];
    int   besti[8];
    #pragma unroll
    for (int m = 0; m < 8; m++) { bestv[m] = CUDART_INF_F; besti[m] = 0; }

    for (int j0 = 0; j0 < BINS_; j0 += 128) {
        float acc[8][8];
        #pragma unroll
        for (int m = 0; m < 8; m++)
            #pragma unroll
            for (int n = 0; n < 8; n++) acc[m][n] = 0.0f;

        for (int k0 = 0; k0 < D_; k0 += 16) {
            #pragma unroll
            for (int it = 0; it < 2; it++) {
                int r = lr + it * 64;
                float4 av = *(const float4*)&g_resid[(size_t)(n0 + r) * D_ + k0 + lk];
                float4 bv = *(const float4*)&cb[(size_t)(j0 + r) * D_ + k0 + lk];
                sm.g.A[lk + 0][r] = av.x; sm.g.A[lk + 1][r] = av.y;
                sm.g.A[lk + 2][r] = av.z; sm.g.A[lk + 3][r] = av.w;
                sm.g.B[lk + 0][r] = bv.x; sm.g.B[lk + 1][r] = bv.y;
                sm.g.B[lk + 2][r] = bv.z; sm.g.B[lk + 3][r] = bv.w;
            }
            __syncthreads();
            #pragma unroll
            for (int k = 0; k < 16; k++) {
                float a[8], b[8];
                *(float4*)&a[0] = *(const float4*)&sm.g.A[k][ty * 8];
                *(float4*)&a[4] = *(const float4*)&sm.g.A[k][ty * 8 + 4];
                *(float4*)&b[0] = *(const float4*)&sm.g.B[k][tx * 8];
                *(float4*)&b[4] = *(const float4*)&sm.g.B[k][tx * 8 + 4];
                #pragma unroll
                for (int m = 0; m < 8; m++)
                    #pragma unroll
                    for (int n = 0; n < 8; n++)
                        acc[m][n] += a[m] * b[n];
            }
            __syncthreads();
        }

        // epilogue: distances + running argmin
        #pragma unroll
        for (int n = 0; n < 8; n++) {
            int   j  = j0 + tx * 8 + n;
            float cn = __ldg(&cnorm[j]);
            #pragma unroll
            for (int m = 0; m < 8; m++) {
                float d = cn - 2.0f * acc[m][n];
                if (d < bestv[m] || (d == bestv[m] && j < besti[m])) {
                    bestv[m] = d;
                    besti[m] = j;
                }
            }
        }
    }

    // cross-thread reduce: row r = ty*8+m is held by 16 tx-threads
    __syncthreads();
    #pragma unroll
    for (int m = 0; m < 8; m++) {
        sm.r.v[ty * 8 + m][tx]   = bestv[m];
        sm.r.idx[ty * 8 + m][tx] = besti[m];
    }
    __syncthreads();
    if (tid < 128) {
        float bv = sm.r.v[tid][0];
        int   bi = sm.r.idx[tid][0];
        #pragma unroll
        for (int xk = 1; xk < 16; xk++) {
            float v = sm.r.v[tid][xk];
            int   i = sm.r.idx[tid][xk];
            if (v < bv || (v == bv && i < bi)) { bv = v; bi = i; }
        }
        codes[n0 + tid] = bi;
    }
}

// ---------------------------------------------------------------------------
// update: q = cb[idx]; loss += sum((r - q)^2); r -= q
__global__ __launch_bounds__(256) void update_kernel(
    const float* __restrict__ cb_all, int q_layer)
{
    __shared__ float warp_ss[8];
    const float* cb    = cb_all + (size_t)q_layer * BINS_ * D_;
    const int*   codes = g_codes + q_layer * N_;

    int warp = threadIdx.x >> 5;
    int lane = threadIdx.x & 31;
    int n    = blockIdx.x * 8 + warp;

    const float4* q4 = (const float4*)(cb + (size_t)codes[n] * D_);
    float4* r4 = (float4*)(g_resid + (size_t)n * D_);

    float ss = 0.0f;
    #pragma unroll
    for (int i = 0; i < 2; i++) {
        int e = lane + 32 * i;
        float4 r = r4[e];
        float4 q = q4[e];
        float dx = r.x - q.x, dy = r.y - q.y, dz = r.z - q.z, dw = r.w - q.w;
        ss += dx * dx + dy * dy + dz * dz + dw * dw;
        r4[e] = make_float4(dx, dy, dz, dw);
    }
    #pragma unroll
    for (int o = 16; o > 0; o >>= 1) ss += __shfl_xor_sync(0xFFFFFFFFu, ss, o);
    if (lane == 0) warp_ss[warp] = ss;
    __syncthreads();
    if (threadIdx.x == 0) {
        float s = 0.0f;
        #pragma unroll
        for (int w = 0; w < 8; w++) s += warp_ss[w];
        atomicAdd(&g_loss, s);
    }
}

// ---------------------------------------------------------------------------
// quantized = x - residual_final, transposed back to [B][D][T]
__global__ void finalize_out_kernel(const float* __restrict__ x,
                                    float* __restrict__ out)
{
    __shared__ float tile[32][33];
    int b  = blockIdx.z;
    int d0 = blockIdx.y * 32;
    int t0 = blockIdx.x * 32;
    int tx = threadIdx.x;
    int ty = threadIdx.y;
    #pragma unroll
    for (int i = ty; i < 32; i += 8)
        tile[i][tx] = g_resid[((size_t)b * T_ + t0 + i) * D_ + d0 + tx];
    __syncthreads();
    #pragma unroll
    for (int i = ty; i < 32; i += 8) {
        size_t xi = (size_t)b * D_ * T_ + (size_t)(d0 + i) * T_ + t0 + tx;
        out[xi] = x[xi] - tile[tx][i];
    }
}

// ---------------------------------------------------------------------------
__global__ void codes_to_float_kernel(float* __restrict__ out) {
    int i = blockIdx.x * 256 + threadIdx.x;
    if (i < CODES_ELEMS) out[i] = (float)g_codes[i];
}

__global__ void loss_write_kernel(float* __restrict__ out) {
    out[0] = g_loss * (1.0f / ((float)NQ_ * (float)N_ * (float)D_));
}

// ---------------------------------------------------------------------------
extern "C" void kernel_launch(void* const* d_in, const int* in_sizes, int n_in,
                              void* d_out, int out_size)
{
    const float* x  = (const float*)d_in[0];   // [B, D, T]
    const float* cb = (const float*)d_in[1];   // [NQ, BINS, D]
    float* out = (float*)d_out;

    zero_loss_kernel<<<1, 1>>>();
    cnorm_kernel<<<(NQ_ * BINS_) / 8, 256>>>(cb);
    {
        dim3 grid(T_ / 32, D_ / 32, B_);
        dim3 blk(32, 8);
        transpose_in_kernel<<<grid, blk>>>(x);
    }
    for (int q = 0; q < NQ_; q++) {
        dist_argmin_kernel<<<N_ / 128, 256>>>(cb, q);
        update_kernel<<<N_ / 8, 256>>>(cb, q);
    }
    {
        dim3 grid(T_ / 32, D_ / 32, B_);
        dim3 blk(32, 8);
        finalize_out_kernel<<<grid, blk>>>(x, out);
    }
    codes_to_float_kernel<<<(CODES_ELEMS + 255) / 256, 256>>>(out + QUANT_ELEMS);
    loss_write_kernel<<<1, 1>>>(out + QUANT_ELEMS + CODES_ELEMS);
}